// round 3
// baseline (speedup 1.0000x reference)
#include <cuda_runtime.h>
#include <math_constants.h>

#define BSZ      1024
#define KCOLS    66560              // BSZ + 65536
#define KV4      (KCOLS / 4)        // 16640 float4 per row = 65 per thread
#define NTHREADS 256
#define NWARPS   (NTHREADS / 32)
#define NGROUPS  16                 // 16 groups of 4 float4 + 1 remainder per thread
#define CAP      4096
#define TCAND    2.5f

__device__ float    g_row_loss[BSZ];
__device__ unsigned g_done = 0;     // reset by last block each launch -> replay-safe

// Rare path: capture candidates from one float4 (≈2.4% of vectors hit this).
__device__ __forceinline__ void capture4(float4 x, int v, int row,
                                         float& mxo, int* s_cnt, float* s_cand)
{
    const float c[4] = {x.x, x.y, x.z, x.w};
    const int base = v * 4;
    #pragma unroll
    for (int q = 0; q < 4; q++) {
        if (c[q] >= TCAND && (base + q) != row) {
            mxo = fmaxf(mxo, c[q]);
            int p = atomicAdd(s_cnt, 1);
            if (p < CAP) s_cand[p] = c[q];
        }
    }
}

__global__ __launch_bounds__(NTHREADS) void wl_row_kernel(const float* __restrict__ logits,
                                                          float* __restrict__ out)
{
    const int row = blockIdx.x;
    const float4* __restrict__ rp =
        reinterpret_cast<const float4*>(logits + (size_t)row * KCOLS);

    __shared__ float s_cand[CAP];
    __shared__ int   s_cnt;
    __shared__ float s_sum[NWARPS];
    __shared__ float s_max[NWARPS];
    __shared__ float s_par[4];          // inv, m, dl, fast-flag
    __shared__ int   s_last;

    const int tid = threadIdx.x;
    if (tid == 0) s_cnt = 0;
    __syncthreads();

    // ---- Pass 1: branch-free streaming core, one rare branch per 16 elements ---
    float s0 = 0.f, s1 = 0.f, s2 = 0.f, s3 = 0.f;
    float mxo = -CUDART_INF_F;          // off-diag candidate max (exact off-diag
                                        // max whenever any off-diag elem >= TCAND)
    for (int g = 0; g < NGROUPS; g++) {
        const int vb = tid + g * (4 * NTHREADS);
        // 4 unconditional vector loads, no control flow between them (MLP=4)
        float4 x0 = rp[vb];
        float4 x1 = rp[vb + NTHREADS];
        float4 x2 = rp[vb + 2 * NTHREADS];
        float4 x3 = rp[vb + 3 * NTHREADS];

        s0 += (__expf(x0.x) + __expf(x1.x)) + (__expf(x2.x) + __expf(x3.x));
        s1 += (__expf(x0.y) + __expf(x1.y)) + (__expf(x2.y) + __expf(x3.y));
        s2 += (__expf(x0.z) + __expf(x1.z)) + (__expf(x2.z) + __expf(x3.z));
        s3 += (__expf(x0.w) + __expf(x1.w)) + (__expf(x2.w) + __expf(x3.w));

        float m0 = fmaxf(fmaxf(x0.x, x0.y), fmaxf(x0.z, x0.w));
        float m1 = fmaxf(fmaxf(x1.x, x1.y), fmaxf(x1.z, x1.w));
        float m2 = fmaxf(fmaxf(x2.x, x2.y), fmaxf(x2.z, x2.w));
        float m3 = fmaxf(fmaxf(x3.x, x3.y), fmaxf(x3.z, x3.w));
        float mg = fmaxf(fmaxf(m0, m1), fmaxf(m2, m3));

        if (mg >= TCAND) {              // ~9.5% of groups on N(0,1) data
            if (m0 >= TCAND) capture4(x0, vb,                row, mxo, &s_cnt, s_cand);
            if (m1 >= TCAND) capture4(x1, vb + NTHREADS,     row, mxo, &s_cnt, s_cand);
            if (m2 >= TCAND) capture4(x2, vb + 2 * NTHREADS, row, mxo, &s_cnt, s_cand);
            if (m3 >= TCAND) capture4(x3, vb + 3 * NTHREADS, row, mxo, &s_cnt, s_cand);
        }
    }
    {   // remainder: one float4 per thread (group 16)
        const int v = tid + NGROUPS * (4 * NTHREADS);   // < KV4 by construction
        float4 x = rp[v];
        s0 += __expf(x.x); s1 += __expf(x.y); s2 += __expf(x.z); s3 += __expf(x.w);
        float mg = fmaxf(fmaxf(x.x, x.y), fmaxf(x.z, x.w));
        if (mg >= TCAND) capture4(x, v, row, mxo, &s_cnt, s_cand);
    }

    float sum = (s0 + s1) + (s2 + s3);
    #pragma unroll
    for (int o = 16; o; o >>= 1) {
        sum += __shfl_xor_sync(0xffffffffu, sum, o);
        mxo  = fmaxf(mxo, __shfl_xor_sync(0xffffffffu, mxo, o));
    }
    if ((tid & 31) == 0) { s_sum[tid >> 5] = sum; s_max[tid >> 5] = mxo; }
    __syncthreads();

    if (tid == 0) {
        float S = 0.f, M = -CUDART_INF_F;
        #pragma unroll
        for (int i = 0; i < NWARPS; i++) { S += s_sum[i]; M = fmaxf(M, s_max[i]); }
        float dl       = logits[(size_t)row * KCOLS + row];     // cache hit
        float neg_mean = (S - __expf(dl)) * (1.0f / (float)(KCOLS - 1));
        float inv      = 1.0f / neg_mean;
        // g(l)=l*exp(l)*inv monotone for l >= -1; M >= TCAND > 0 on fast path, so
        // g(M) is the EXACT off-diagonal max of u. Row max m = max(g(M), dl).
        float gmo = M * __expf(M) * inv;
        float m   = fmaxf(gmo, dl);
        float gT  = TCAND * __expf(TCAND) * inv;  // bound on any non-candidate u
        bool fast = (M >= TCAND) && (neg_mean > 0.f) &&
                    (gT <= m - 30.f) && (s_cnt <= CAP);
        s_par[0] = inv; s_par[1] = m; s_par[2] = dl; s_par[3] = fast ? 1.f : 0.f;
    }
    __syncthreads();

    const float inv = s_par[0], m = s_par[1], dl = s_par[2];
    const bool  fast = (s_par[3] != 0.f);

    if (fast) {
        // ---- Pass 2 (fast): captured candidates only — zero memory re-read -----
        const int nc = s_cnt;
        float sl = 0.f;
        for (int i = tid; i < nc; i += NTHREADS) {
            float l = s_cand[i];
            sl += __expf(l * __expf(l) * inv - m);
        }
        #pragma unroll
        for (int o = 16; o; o >>= 1) sl += __shfl_xor_sync(0xffffffffu, sl, o);
        if ((tid & 31) == 0) s_sum[tid >> 5] = sl;
        __syncthreads();
        if (tid == 0) {
            float s = __expf(dl - m);           // diagonal term (u_ii = dl)
            #pragma unroll
            for (int i = 0; i < NWARPS; i++) s += s_sum[i];
            g_row_loss[row] = m + logf(s) - dl;
        }
    } else {
        // ---- Pass 2 (robust fallback): full online-LSE re-read ------------------
        float mt = -CUDART_INF_F, st = 0.f;
        for (int v = tid; v < KV4; v += NTHREADS) {
            float4 x = rp[v];
            float c[4] = {x.x, x.y, x.z, x.w};
            #pragma unroll
            for (int q = 0; q < 4; q++) {
                int   j = v * 4 + q;
                float u = (j == row) ? dl : c[q] * __expf(c[q]) * inv;
                float nm = fmaxf(mt, u);
                st = st * __expf(mt - nm) + __expf(u - nm);
                mt = nm;
            }
        }
        #pragma unroll
        for (int o = 16; o; o >>= 1) {
            float om = __shfl_xor_sync(0xffffffffu, mt, o);
            float os = __shfl_xor_sync(0xffffffffu, st, o);
            float nm = fmaxf(mt, om);
            st = st * __expf(mt - nm) + os * __expf(om - nm);
            mt = nm;
        }
        if ((tid & 31) == 0) { s_sum[tid >> 5] = st; s_max[tid >> 5] = mt; }
        __syncthreads();
        if (tid == 0) {
            float m2 = -CUDART_INF_F, s2v = 0.f;
            #pragma unroll
            for (int i = 0; i < NWARPS; i++) m2 = fmaxf(m2, s_max[i]);
            #pragma unroll
            for (int i = 0; i < NWARPS; i++) s2v += s_sum[i] * __expf(s_max[i] - m2);
            g_row_loss[row] = m2 + logf(s2v) - dl;
        }
    }

    // ---- Fused final reduction: last finishing block sums the 1024 row losses --
    if (tid == 0) {
        __threadfence();
        unsigned t = atomicAdd(&g_done, 1u);
        s_last = (t == (unsigned)(gridDim.x - 1));
    }
    __syncthreads();
    if (s_last) {
        float v = 0.f;
        #pragma unroll
        for (int i = tid; i < BSZ; i += NTHREADS) v += __ldcg(&g_row_loss[i]);
        #pragma unroll
        for (int o = 16; o; o >>= 1) v += __shfl_xor_sync(0xffffffffu, v, o);
        if ((tid & 31) == 0) s_sum[tid >> 5] = v;
        __syncthreads();
        if (tid == 0) {
            float t = 0.f;
            #pragma unroll
            for (int i = 0; i < NWARPS; i++) t += s_sum[i];
            out[0] = t * (1.0f / (float)BSZ);
            g_done = 0;                         // reset for next graph replay
        }
    }
}

extern "C" void kernel_launch(void* const* d_in, const int* in_sizes, int n_in,
                              void* d_out, int out_size)
{
    const float* logits = (const float*)d_in[0];
    (void)in_sizes; (void)n_in; (void)out_size;
    wl_row_kernel<<<BSZ, NTHREADS>>>(logits, (float*)d_out);
}

// round 4
// speedup vs baseline: 1.1461x; 1.1461x over previous
#include <cuda_runtime.h>
#include <math_constants.h>

#define BSZ      1024
#define KCOLS    66560              // BSZ + 65536
#define KV4      (KCOLS / 4)        // 16640 float4 per row
#define NTHREADS 256
#define NWARPS   (NTHREADS / 32)
#define CAP      3584               // candidate slots (expected ~410 used)
#define TCAND    2.5f

#define CHUNK_F4   1024             // float4 per full chunk (16 KB)
#define CHUNK_B    16384
#define NFULL      16               // 16 * 16KB = 256 KB
#define TAIL_B     4096             // + 4 KB tail = 266,240 B = one row
#define NCHUNKS    17

__device__ float    g_row_loss[BSZ];
__device__ unsigned g_done = 0;     // reset by last block each launch -> replay-safe

__device__ __forceinline__ unsigned su32(const void* p) {
    return (unsigned)__cvta_generic_to_shared(p);
}
__device__ __forceinline__ void mbar_init(unsigned mbar, unsigned cnt) {
    asm volatile("mbarrier.init.shared.b64 [%0], %1;" :: "r"(mbar), "r"(cnt) : "memory");
}
__device__ __forceinline__ void mbar_expect_tx(unsigned mbar, unsigned bytes) {
    asm volatile("mbarrier.arrive.expect_tx.shared.b64 _, [%0], %1;"
                 :: "r"(mbar), "r"(bytes) : "memory");
}
__device__ __forceinline__ void bulk_g2s(unsigned dst, const void* src,
                                         unsigned bytes, unsigned mbar) {
    asm volatile("cp.async.bulk.shared::cluster.global.mbarrier::complete_tx::bytes "
                 "[%0], [%1], %2, [%3];"
                 :: "r"(dst), "l"(src), "r"(bytes), "r"(mbar) : "memory");
}
__device__ __forceinline__ void mbar_wait(unsigned mbar, unsigned phase) {
    asm volatile(
        "{\n\t.reg .pred P;\n\t"
        "WAIT_%=:\n\t"
        "mbarrier.try_wait.parity.acquire.cta.shared::cta.b64 P, [%0], %1, 0x989680;\n\t"
        "@P bra.uni DONE_%=;\n\t"
        "bra.uni WAIT_%=;\n\t"
        "DONE_%=:\n\t}"
        :: "r"(mbar), "r"(phase) : "memory");
}

__global__ __launch_bounds__(NTHREADS) void wl_row_kernel(const float* __restrict__ logits,
                                                          float* __restrict__ out)
{
    const int row = blockIdx.x;
    const char* __restrict__ rowb =
        reinterpret_cast<const char*>(logits + (size_t)row * KCOLS);

    __shared__ __align__(16) float4 s_tile[2][CHUNK_F4];       // 32 KB, 2 stages
    __shared__ __align__(8)  unsigned long long s_mbar_store[2];
    __shared__ float s_cand[CAP];
    __shared__ int   s_cnt;
    __shared__ float s_sum[NWARPS];
    __shared__ float s_max[NWARPS];
    __shared__ float s_par[4];          // inv, m, dl, fast-flag
    __shared__ int   s_last;

    const int tid = threadIdx.x;
    const unsigned mb0 = su32(&s_mbar_store[0]);
    const unsigned mb1 = su32(&s_mbar_store[1]);
    const unsigned tl0 = su32(&s_tile[0][0]);
    const unsigned tl1 = su32(&s_tile[1][0]);

    if (tid == 0) {
        s_cnt = 0;
        mbar_init(mb0, 1);
        mbar_init(mb1, 1);
        asm volatile("fence.proxy.async.shared::cta;" ::: "memory");
    }
    __syncthreads();

    // Prologue: prefetch chunks 0 and 1
    if (tid == 0) {
        mbar_expect_tx(mb0, CHUNK_B);
        bulk_g2s(tl0, rowb, CHUNK_B, mb0);
        mbar_expect_tx(mb1, CHUNK_B);
        bulk_g2s(tl1, rowb + CHUNK_B, CHUNK_B, mb1);
    }

    // ---- Pass 1: consume SMEM chunks; sum(exp), predicated candidate capture ---
    float s0 = 0.f, s1 = 0.f, s2 = 0.f, s3 = 0.f;
    float mxo = -CUDART_INF_F;          // off-diag candidate max (exact off-diag
                                        // max whenever any off-diag elem >= TCAND)
    for (int c = 0; c < NCHUNKS; c++) {
        const int      st = c & 1;
        const unsigned ph = (unsigned)((c >> 1) & 1);
        mbar_wait(st ? mb1 : mb0, ph);

        if (c < NFULL) {
            #pragma unroll
            for (int k = 0; k < 4; k++) {
                const int l4 = tid + k * NTHREADS;
                float4 x = s_tile[st][l4];
                s0 += __expf(x.x); s1 += __expf(x.y);
                s2 += __expf(x.z); s3 += __expf(x.w);
                const int gb = 4 * (c * CHUNK_F4 + l4);
                if (x.x >= TCAND && gb + 0 != row) { mxo = fmaxf(mxo, x.x); int p = atomicAdd(&s_cnt, 1); if (p < CAP) s_cand[p] = x.x; }
                if (x.y >= TCAND && gb + 1 != row) { mxo = fmaxf(mxo, x.y); int p = atomicAdd(&s_cnt, 1); if (p < CAP) s_cand[p] = x.y; }
                if (x.z >= TCAND && gb + 2 != row) { mxo = fmaxf(mxo, x.z); int p = atomicAdd(&s_cnt, 1); if (p < CAP) s_cand[p] = x.z; }
                if (x.w >= TCAND && gb + 3 != row) { mxo = fmaxf(mxo, x.w); int p = atomicAdd(&s_cnt, 1); if (p < CAP) s_cand[p] = x.w; }
            }
        } else {                        // tail chunk: 256 float4
            float4 x = s_tile[st][tid];
            s0 += __expf(x.x); s1 += __expf(x.y);
            s2 += __expf(x.z); s3 += __expf(x.w);
            const int gb = 4 * (c * CHUNK_F4 + tid);
            if (x.x >= TCAND && gb + 0 != row) { mxo = fmaxf(mxo, x.x); int p = atomicAdd(&s_cnt, 1); if (p < CAP) s_cand[p] = x.x; }
            if (x.y >= TCAND && gb + 1 != row) { mxo = fmaxf(mxo, x.y); int p = atomicAdd(&s_cnt, 1); if (p < CAP) s_cand[p] = x.y; }
            if (x.z >= TCAND && gb + 2 != row) { mxo = fmaxf(mxo, x.z); int p = atomicAdd(&s_cnt, 1); if (p < CAP) s_cand[p] = x.z; }
            if (x.w >= TCAND && gb + 3 != row) { mxo = fmaxf(mxo, x.w); int p = atomicAdd(&s_cnt, 1); if (p < CAP) s_cand[p] = x.w; }
        }

        __syncthreads();                // all reads of stage st complete
        if (tid == 0 && c + 2 < NCHUNKS) {
            const unsigned nb = (c + 2 < NFULL) ? CHUNK_B : TAIL_B;
            const unsigned mb = st ? mb1 : mb0;     // stage (c+2)&1 == st
            mbar_expect_tx(mb, nb);
            bulk_g2s(st ? tl1 : tl0, rowb + (size_t)(c + 2) * CHUNK_B, nb, mb);
        }
    }

    float sum = (s0 + s1) + (s2 + s3);
    #pragma unroll
    for (int o = 16; o; o >>= 1) {
        sum += __shfl_xor_sync(0xffffffffu, sum, o);
        mxo  = fmaxf(mxo, __shfl_xor_sync(0xffffffffu, mxo, o));
    }
    if ((tid & 31) == 0) { s_sum[tid >> 5] = sum; s_max[tid >> 5] = mxo; }
    __syncthreads();

    if (tid == 0) {
        float S = 0.f, M = -CUDART_INF_F;
        #pragma unroll
        for (int i = 0; i < NWARPS; i++) { S += s_sum[i]; M = fmaxf(M, s_max[i]); }
        float dl       = logits[(size_t)row * KCOLS + row];
        float neg_mean = (S - __expf(dl)) * (1.0f / (float)(KCOLS - 1));
        float inv      = 1.0f / neg_mean;
        // g(l)=l*exp(l)*inv monotone for l >= -1; M >= TCAND > 0 on fast path, so
        // g(M) is the EXACT off-diagonal max of u. Row max m = max(g(M), dl).
        float gmo = M * __expf(M) * inv;
        float m   = fmaxf(gmo, dl);
        float gT  = TCAND * __expf(TCAND) * inv;  // bound on any non-candidate u
        bool fast = (M >= TCAND) && (neg_mean > 0.f) &&
                    (gT <= m - 30.f) && (s_cnt <= CAP);
        s_par[0] = inv; s_par[1] = m; s_par[2] = dl; s_par[3] = fast ? 1.f : 0.f;
    }
    __syncthreads();

    const float inv = s_par[0], m = s_par[1], dl = s_par[2];
    const bool  fast = (s_par[3] != 0.f);

    if (fast) {
        // ---- Pass 2 (fast): captured candidates only — zero memory re-read -----
        const int nc = s_cnt;
        float sl = 0.f;
        for (int i = tid; i < nc; i += NTHREADS) {
            float l = s_cand[i];
            sl += __expf(l * __expf(l) * inv - m);
        }
        #pragma unroll
        for (int o = 16; o; o >>= 1) sl += __shfl_xor_sync(0xffffffffu, sl, o);
        if ((tid & 31) == 0) s_sum[tid >> 5] = sl;
        __syncthreads();
        if (tid == 0) {
            float s = __expf(dl - m);           // diagonal term (u_ii = dl)
            #pragma unroll
            for (int i = 0; i < NWARPS; i++) s += s_sum[i];
            g_row_loss[row] = m + logf(s) - dl;
        }
    } else {
        // ---- Pass 2 (robust fallback): full online-LSE re-read from GMEM -------
        const float4* __restrict__ rp = reinterpret_cast<const float4*>(rowb);
        float mt = -CUDART_INF_F, st2 = 0.f;
        for (int v = tid; v < KV4; v += NTHREADS) {
            float4 x = rp[v];
            float cc[4] = {x.x, x.y, x.z, x.w};
            #pragma unroll
            for (int q = 0; q < 4; q++) {
                int   j = v * 4 + q;
                float u = (j == row) ? dl : cc[q] * __expf(cc[q]) * inv;
                float nm = fmaxf(mt, u);
                st2 = st2 * __expf(mt - nm) + __expf(u - nm);
                mt = nm;
            }
        }
        #pragma unroll
        for (int o = 16; o; o >>= 1) {
            float om = __shfl_xor_sync(0xffffffffu, mt, o);
            float os = __shfl_xor_sync(0xffffffffu, st2, o);
            float nm = fmaxf(mt, om);
            st2 = st2 * __expf(mt - nm) + os * __expf(om - nm);
            mt = nm;
        }
        if ((tid & 31) == 0) { s_sum[tid >> 5] = st2; s_max[tid >> 5] = mt; }
        __syncthreads();
        if (tid == 0) {
            float m2 = -CUDART_INF_F, s2v = 0.f;
            #pragma unroll
            for (int i = 0; i < NWARPS; i++) m2 = fmaxf(m2, s_max[i]);
            #pragma unroll
            for (int i = 0; i < NWARPS; i++) s2v += s_sum[i] * __expf(s_max[i] - m2);
            g_row_loss[row] = m2 + logf(s2v) - dl;
        }
    }

    // ---- Fused final reduction: last finishing block sums the 1024 row losses --
    if (tid == 0) {
        __threadfence();
        unsigned t = atomicAdd(&g_done, 1u);
        s_last = (t == (unsigned)(gridDim.x - 1));
    }
    __syncthreads();
    if (s_last) {
        float v = 0.f;
        #pragma unroll
        for (int i = tid; i < BSZ; i += NTHREADS) v += __ldcg(&g_row_loss[i]);
        #pragma unroll
        for (int o = 16; o; o >>= 1) v += __shfl_xor_sync(0xffffffffu, v, o);
        if ((tid & 31) == 0) s_sum[tid >> 5] = v;
        __syncthreads();
        if (tid == 0) {
            float t = 0.f;
            #pragma unroll
            for (int i = 0; i < NWARPS; i++) t += s_sum[i];
            out[0] = t * (1.0f / (float)BSZ);
            g_done = 0;                         // reset for next graph replay
        }
    }
}

extern "C" void kernel_launch(void* const* d_in, const int* in_sizes, int n_in,
                              void* d_out, int out_size)
{
    const float* logits = (const float*)d_in[0];
    (void)in_sizes; (void)n_in; (void)out_size;
    wl_row_kernel<<<BSZ, NTHREADS>>>(logits, (float*)d_out);
}